// round 9
// baseline (speedup 1.0000x reference)
#include <cuda_runtime.h>
#include <cstdint>

#define N_NODES 500000
#define N_EDGES 1250000
#define N_GRAPH 64

typedef unsigned long long u64;
typedef unsigned int u32;

// ---------------- scratch (device globals; no allocation allowed) -----------
__device__ float g_x[N_NODES * 64];
__device__ float g_m[N_NODES * 64];
__device__ float g_agg[N_NODES * 64];
__device__ float g_u[4 * 100 * 64];
__device__ float g_Bm[4 * 64 * 64];
__device__ float g_v[4 * 100 * 64];
__device__ float g_t0m[100 * 64];
__device__ float g_gsum[64 * 64];

// ---------------- helpers ------------------------------------------------------
__device__ __forceinline__ float sigm(float x)  { return __fdividef(1.0f, 1.0f + __expf(-x)); }
__device__ __forceinline__ float tanh_(float x) { return __fdividef(2.0f, 1.0f + __expf(-2.0f * x)) - 1.0f; }
__device__ __forceinline__ float elu_(float x)  { return x > 0.0f ? x : (__expf(x) - 1.0f); }

__device__ __forceinline__ float tf32r(float x) {
    u32 r;
    asm("cvt.rna.tf32.f32 %0, %1;" : "=r"(r) : "f"(x));
    return __uint_as_float(r);
}
__device__ __forceinline__ u32 tf32u(float x) {
    u32 r;
    asm("cvt.rna.tf32.f32 %0, %1;" : "=r"(r) : "f"(x));
    return r;
}

#define F4F(v, e) ((e) == 0 ? (v).x : (e) == 1 ? (v).y : (e) == 2 ? (v).z : (v).w)
#define F4U(v, e) __float_as_uint(F4F(v, e))

// m16n8k8 tf32 mma
#define MMA4(c, a0, a1, a2, a3, b0, b1)                                          \
    asm volatile("mma.sync.aligned.m16n8k8.row.col.f32.tf32.tf32.f32 "           \
                 "{%0,%1,%2,%3}, {%4,%5,%6,%7}, {%8,%9}, {%0,%1,%2,%3};"          \
                 : "+f"((c)[0]), "+f"((c)[1]), "+f"((c)[2]), "+f"((c)[3])        \
                 : "r"(a0), "r"(a1), "r"(a2), "r"(a3), "r"(b0), "r"(b1))

// ---------------- precompute (also zeroes g_gsum) -------------------------------
__global__ void k_pre1(const float* __restrict__ ztab, const float* __restrict__ tfW,
                       const float* __restrict__ tfb, const float* __restrict__ ggcW) {
    int i = blockIdx.x * blockDim.x + threadIdx.x;
    if (i < 25600) {
        int j = i / 6400, r = (i % 6400) / 64, o = i % 64;
        const float* zt = ztab + (j + 1) * 6400 + r * 64;
        const float* w  = tfW + j * 8192 + o * 128 + 64;
        float acc = tfb[j * 64 + o];
        #pragma unroll
        for (int k = 0; k < 64; k++) acc += zt[k] * w[k];
        g_u[i] = acc;
    } else if (i < 41984) {
        int ii = i - 25600;
        int j = ii / 4096, o = (ii % 4096) / 64, k = ii % 64;
        const float* g = ggcW + (j + 1) * 4096 + o;
        const float* w = tfW + j * 8192 + k;
        float acc = 0.f;
        #pragma unroll
        for (int t = 0; t < 64; t++) acc += w[t * 128] * g[t * 64];
        g_Bm[ii] = acc;
    } else if (i < 48384) {
        int ii = i - 41984;
        int r = ii / 64, o = ii % 64;
        float acc = 0.f;
        #pragma unroll
        for (int k = 0; k < 64; k++) acc += ztab[r * 64 + k] * ggcW[k * 64 + o];
        g_t0m[ii] = acc;
    } else if (i < 52480) {
        g_gsum[i - 48384] = 0.f;
    }
}

__global__ void k_pre2(const float* __restrict__ ggcW) {
    int i = blockIdx.x * blockDim.x + threadIdx.x;
    if (i >= 25600) return;
    int j = i / 6400, r = (i % 6400) / 64, o = i % 64;
    const float* urow = g_u + j * 6400 + r * 64;
    const float* g = ggcW + (j + 1) * 4096 + o;
    float acc = 0.f;
    #pragma unroll
    for (int t = 0; t < 64; t++) acc += urow[t] * g[t * 64];
    g_v[i] = acc;
}

// ---------------- layer 0: lookups + zero agg -----------------------------------
__global__ void k_layer0(const int* __restrict__ z, const float* __restrict__ ztab) {
    int idx = blockIdx.x * 256 + threadIdx.x;  // N_NODES*16
    int n = idx >> 4, c = idx & 15;
    int r = __ldg(z + n);
    float4 a = ((const float4*)(ztab + r * 64))[c];
    ((float4*)(g_x + (size_t)n * 64))[c] = a;
    float4 b = ((const float4*)(g_t0m + r * 64))[c];
    ((float4*)(g_m + (size_t)n * 64))[c] = b;
    ((float4*)(g_agg + (size_t)n * 64))[c] = make_float4(0.f, 0.f, 0.f, 0.f);
}

// ---------------- edge scatter: agg[dst] += m[src] -------------------------------
__global__ void k_scatter(const int* __restrict__ src, const int* __restrict__ dst) {
    int idx = blockIdx.x * 256 + threadIdx.x;  // N_EDGES*16
    int e = idx >> 4, c = idx & 15;
    int s = __ldg(src + e), t = __ldg(dst + e);
    float4 v = ((const float4*)(g_m + (size_t)s * 64))[c];
    float* o = g_agg + (size_t)t * 64 + c * 4;
    atomicAdd(o + 0, v.x);
    atomicAdd(o + 1, v.y);
    atomicAdd(o + 2, v.z);
    atomicAdd(o + 3, v.w);
}

// ================= tensor (mma.sync tf32) layer kernels ==========================
// Fragment-major permuted layout: P[strip][half][lane][j], lane stride 20 floats
// (16B-aligned; lanes 0..7 -> banks {0,20,8,28,16,4,24,12}: LDS.128 conflict-free).
// element P[s][i][qr*4+qc][j] = A[s*16 + i*8 + qr][qc + 4j]

#define GROWS   64
#define GB_BIAS 0                      // 384
#define GB_AAG  384                    // 4 strips * 2 * 32 * 20 = 5120
#define GB_AX   5504                   // 5120
#define GB_B    10624                  // 24 ntiles * 32 * 20 = 15360
#define GB_TOT  25984
#define GRU_SMEM (GB_TOT * 4)          // 103936 B -> 2 CTAs/SM

__global__ void __launch_bounds__(256, 2) k_gru_t(
        const float* __restrict__ wih, const float* __restrict__ whh,
        const float* __restrict__ bih, const float* __restrict__ bhh,
        const int* __restrict__ n2s, const int* __restrict__ s2g, int last) {
    extern __shared__ float sm[];
    float* sb = sm + GB_BIAS;
    int tid = threadIdx.x;
    int n0 = blockIdx.x * GROWS;

    // phase 1: stage wih permuted into GB_B
    for (int idx = tid; idx < 3072; idx += 256) {
        int row = idx >> 4, f4 = idx & 15;
        int nt = row >> 3, qr8 = row & 7;
        float4 v = ((const float4*)(wih + row * 64))[f4];
        float* p = sm + GB_B + (nt * 32 + qr8 * 4) * 20 + f4;
        p[0]  = tf32r(v.x);
        p[20] = tf32r(v.y);
        p[40] = tf32r(v.z);
        p[60] = tf32r(v.w);
    }
    __syncthreads();

    int w = tid >> 5, lane = tid & 31;
    int qr = lane >> 2, qc = lane & 3;

    // prefetch wih frags: warp w owns ntiles {w, w+8, w+16} -> d in [8w, 8w+8)
    float4 Bi4[3][4];
    #pragma unroll
    for (int g = 0; g < 3; g++) {
        const float4* pb = (const float4*)(sm + GB_B + ((w + 8 * g) * 32 + lane) * 20);
        #pragma unroll
        for (int j4 = 0; j4 < 4; j4++) Bi4[g][j4] = pb[j4];
    }
    __syncthreads();

    // phase 2: whh over GB_B; biases; A tiles (agg rounded, x raw); re-zero agg
    for (int i = tid; i < 384; i += 256) sb[i] = (i < 192) ? bih[i] : bhh[i - 192];
    for (int idx = tid; idx < 3072; idx += 256) {
        int row = idx >> 4, f4 = idx & 15;
        int nt = row >> 3, qr8 = row & 7;
        float4 v = ((const float4*)(whh + row * 64))[f4];
        float* p = sm + GB_B + (nt * 32 + qr8 * 4) * 20 + f4;
        p[0]  = tf32r(v.x);
        p[20] = tf32r(v.y);
        p[40] = tf32r(v.z);
        p[60] = tf32r(v.w);
    }
    for (int idx = tid; idx < GROWS * 16; idx += 256) {
        int row = idx >> 4, f4 = idx & 15;
        int s = row >> 4, ih = (row >> 3) & 1, qr8 = row & 7;
        bool ok = (n0 + row) < N_NODES;
        size_t g = ok ? (size_t)(n0 + row) * 64 : 0;
        int ofs = ((s * 2 + ih) * 32 + qr8 * 4) * 20 + f4;
        float4 va = ((const float4*)(g_agg + g))[f4];
        float* pa = sm + GB_AAG + ofs;
        pa[0]  = tf32r(va.x);
        pa[20] = tf32r(va.y);
        pa[40] = tf32r(va.z);
        pa[60] = tf32r(va.w);
        float4 vx = ((const float4*)(g_x + g))[f4];
        float* px = sm + GB_AX + ofs;
        px[0]  = vx.x;
        px[20] = vx.y;
        px[40] = vx.z;
        px[60] = vx.w;
        if (ok && !last) ((float4*)(g_agg + g))[f4] = make_float4(0.f, 0.f, 0.f, 0.f);
    }
    __syncthreads();

    int d0 = w * 8 + qc * 2;
    int jxo = 2 * w + (qc >> 1);
    int Lx0 = qr * 4 + ((2 * qc) & 3);
    int Lx1 = qr * 4 + ((2 * qc + 1) & 3);

    #pragma unroll 1
    for (int s = 0; s < GROWS / 16; s++) {
        float cgi[3][4] = {}, cgh[3][4] = {};
        // ---- GI = agg @ wih^T (Bi in regs) ----
        const float4* pa0 = (const float4*)(sm + GB_AAG + ((s * 2 + 0) * 32 + lane) * 20);
        const float4* pa1 = (const float4*)(sm + GB_AAG + ((s * 2 + 1) * 32 + lane) * 20);
        #pragma unroll
        for (int kh = 0; kh < 2; kh++) {
            float4 v00 = pa0[kh * 2], v01 = pa0[kh * 2 + 1];
            float4 v10 = pa1[kh * 2], v11 = pa1[kh * 2 + 1];
            u32 A0[8] = {F4U(v00,0), F4U(v00,1), F4U(v00,2), F4U(v00,3),
                         F4U(v01,0), F4U(v01,1), F4U(v01,2), F4U(v01,3)};
            u32 A1[8] = {F4U(v10,0), F4U(v10,1), F4U(v10,2), F4U(v10,3),
                         F4U(v11,0), F4U(v11,1), F4U(v11,2), F4U(v11,3)};
            #pragma unroll
            for (int k2 = 0; k2 < 4; k2++) {
                #pragma unroll
                for (int g = 0; g < 3; g++) {
                    MMA4(cgi[g], A0[2 * k2], A1[2 * k2], A0[2 * k2 + 1], A1[2 * k2 + 1],
                         F4U(Bi4[g][2 * kh + (k2 >> 1)], (2 * k2) & 3),
                         F4U(Bi4[g][2 * kh + (k2 >> 1)], (2 * k2 + 1) & 3));
                }
            }
        }
        // ---- GH = x @ whh^T (Bh from smem) ----
        const float4* px0 = (const float4*)(sm + GB_AX + ((s * 2 + 0) * 32 + lane) * 20);
        const float4* px1 = (const float4*)(sm + GB_AX + ((s * 2 + 1) * 32 + lane) * 20);
        #pragma unroll
        for (int kh = 0; kh < 2; kh++) {
            float4 v00 = px0[kh * 2], v01 = px0[kh * 2 + 1];
            float4 v10 = px1[kh * 2], v11 = px1[kh * 2 + 1];
            u32 X0[8] = {tf32u(v00.x), tf32u(v00.y), tf32u(v00.z), tf32u(v00.w),
                         tf32u(v01.x), tf32u(v01.y), tf32u(v01.z), tf32u(v01.w)};
            u32 X1[8] = {tf32u(v10.x), tf32u(v10.y), tf32u(v10.z), tf32u(v10.w),
                         tf32u(v11.x), tf32u(v11.y), tf32u(v11.z), tf32u(v11.w)};
            #pragma unroll
            for (int g = 0; g < 3; g++) {
                const float4* pb = (const float4*)(sm + GB_B + ((w + 8 * g) * 32 + lane) * 20)
                                   + kh * 2;
                float4 b0v = pb[0], b1v = pb[1];
                u32 BH[8] = {F4U(b0v,0), F4U(b0v,1), F4U(b0v,2), F4U(b0v,3),
                             F4U(b1v,0), F4U(b1v,1), F4U(b1v,2), F4U(b1v,3)};
                #pragma unroll
                for (int k2 = 0; k2 < 4; k2++) {
                    MMA4(cgh[g], X0[2 * k2], X1[2 * k2], X0[2 * k2 + 1], X1[2 * k2 + 1],
                         BH[2 * k2], BH[2 * k2 + 1]);
                }
            }
        }
        // ---- epilogue ----
        #pragma unroll
        for (int i = 0; i < 2; i++) {
            int r = s * 16 + qr + 8 * i;
            int n = n0 + r;
            int xb = GB_AX + (s * 2 + i) * 32 * 20;
            float xo0 = sm[xb + Lx0 * 20 + jxo];
            float xo1 = sm[xb + Lx1 * 20 + jxo];
            float out[2];
            #pragma unroll
            for (int j = 0; j < 2; j++) {
                int d = d0 + j;
                int ci = 2 * i + j;
                float rr = sigm(cgi[0][ci] + sb[d] + cgh[0][ci] + sb[192 + d]);
                float uu = sigm(cgi[1][ci] + sb[64 + d] + cgh[1][ci] + sb[256 + d]);
                float nn = tanh_(cgi[2][ci] + sb[128 + d] + rr * (cgh[2][ci] + sb[320 + d]));
                out[j] = (1.0f - uu) * nn + uu * (j ? xo1 : xo0);
            }
            if (n < N_NODES) {
                if (!last) {
                    *(float2*)(g_x + (size_t)n * 64 + d0) = make_float2(out[0], out[1]);
                } else {
                    int gofs = __ldg(s2g + __ldg(n2s + n)) * 64;
                    atomicAdd(g_gsum + gofs + d0, out[0]);
                    atomicAdd(g_gsum + gofs + d0 + 1, out[1]);
                }
            }
        }
    }
}

// ---------------- pre: 128-node tile; B in regs; shared buffer staged B then A ---
#define PROWS 128
#define PRE_SMEM (10240 * 4)   // 8 strips * 2 * 32 * 20 == 16 ntiles * 32 * 20

__global__ void __launch_bounds__(256, 2) k_pre_t(
        const int* __restrict__ z, const float* __restrict__ tfW, int j) {
    extern __shared__ float sm[];
    int tid = threadIdx.x;
    int n0 = blockIdx.x * PROWS;

    // phase 1: stage B = [W_left rows 0..63 | Bm rows 64..127] permuted
    const float* tw = tfW + j * 8192;
    const float* bm = g_Bm + j * 4096;
    for (int idx = tid; idx < 2048; idx += 256) {
        int row = idx >> 4, f4 = idx & 15;
        int nt = row >> 3, qr8 = row & 7;
        float4 v = (row < 64) ? ((const float4*)(tw + row * 128))[f4]
                              : ((const float4*)(bm + (row - 64) * 64))[f4];
        float* p = sm + (nt * 32 + qr8 * 4) * 20 + f4;
        p[0]  = tf32r(v.x);
        p[20] = tf32r(v.y);
        p[40] = tf32r(v.z);
        p[60] = tf32r(v.w);
    }
    __syncthreads();

    int w = tid >> 5, lane = tid & 31;
    int qr = lane >> 2, qc = lane & 3;

    float4 B4[2][4];   // warp w owns ntiles {w (xnew), w+8 (m)}
    #pragma unroll
    for (int g = 0; g < 2; g++) {
        const float4* pb = (const float4*)(sm + ((w + 8 * g) * 32 + lane) * 20);
        #pragma unroll
        for (int j4 = 0; j4 < 4; j4++) B4[g][j4] = pb[j4];
    }
    __syncthreads();

    // phase 2: stage A (x raw) over the same buffer
    for (int idx = tid; idx < PROWS * 16; idx += 256) {
        int row = idx >> 4, f4 = idx & 15;
        int s = row >> 4, ih = (row >> 3) & 1, qr8 = row & 7;
        bool ok = (n0 + row) < N_NODES;
        size_t g = ok ? (size_t)(n0 + row) * 64 : 0;
        float4 vx = ((const float4*)(g_x + g))[f4];
        float* px = sm + ((s * 2 + ih) * 32 + qr8 * 4) * 20 + f4;
        px[0]  = vx.x;
        px[20] = vx.y;
        px[40] = vx.z;
        px[60] = vx.w;
    }
    __syncthreads();

    int d0 = w * 8 + qc * 2;

    #pragma unroll 1
    for (int s = 0; s < PROWS / 16; s++) {
        float cx[4] = {}, cm2[4] = {};
        const float4* px0 = (const float4*)(sm + ((s * 2 + 0) * 32 + lane) * 20);
        const float4* px1 = (const float4*)(sm + ((s * 2 + 1) * 32 + lane) * 20);
        #pragma unroll
        for (int kh = 0; kh < 2; kh++) {
            float4 v00 = px0[kh * 2], v01 = px0[kh * 2 + 1];
            float4 v10 = px1[kh * 2], v11 = px1[kh * 2 + 1];
            u32 X0[8] = {tf32u(v00.x), tf32u(v00.y), tf32u(v00.z), tf32u(v00.w),
                         tf32u(v01.x), tf32u(v01.y), tf32u(v01.z), tf32u(v01.w)};
            u32 X1[8] = {tf32u(v10.x), tf32u(v10.y), tf32u(v10.z), tf32u(v10.w),
                         tf32u(v11.x), tf32u(v11.y), tf32u(v11.z), tf32u(v11.w)};
            #pragma unroll
            for (int k2 = 0; k2 < 4; k2++) {
                MMA4(cx, X0[2 * k2], X1[2 * k2], X0[2 * k2 + 1], X1[2 * k2 + 1],
                     F4U(B4[0][2 * kh + (k2 >> 1)], (2 * k2) & 3),
                     F4U(B4[0][2 * kh + (k2 >> 1)], (2 * k2 + 1) & 3));
                MMA4(cm2, X0[2 * k2], X1[2 * k2], X0[2 * k2 + 1], X1[2 * k2 + 1],
                     F4U(B4[1][2 * kh + (k2 >> 1)], (2 * k2) & 3),
                     F4U(B4[1][2 * kh + (k2 >> 1)], (2 * k2 + 1) & 3));
            }
        }
        #pragma unroll
        for (int i = 0; i < 2; i++) {
            int r = s * 16 + qr + 8 * i;
            int n = n0 + r;
            if (n < N_NODES) {
                int zr = __ldg(z + n);
                const float* ur = g_u + j * 6400 + zr * 64;
                const float* vr = g_v + j * 6400 + zr * 64;
                float2 uu = __ldg((const float2*)(ur + d0));
                float2 vv = __ldg((const float2*)(vr + d0));
                *(float2*)(g_x + (size_t)n * 64 + d0) =
                    make_float2(cx[2 * i] + uu.x, cx[2 * i + 1] + uu.y);
                *(float2*)(g_m + (size_t)n * 64 + d0) =
                    make_float2(cm2[2 * i] + vv.x, cm2[2 * i + 1] + vv.y);
            }
        }
    }
}

// ---------------- MLP head -------------------------------------------------------
__global__ void k_head(const float* __restrict__ w1, const float* __restrict__ b1,
                       const float* __restrict__ w2, const float* __restrict__ b2,
                       const float* __restrict__ w3, const float* __restrict__ b3,
                       float* __restrict__ out) {
    int g = threadIdx.x;
    if (g >= 64) return;
    const float* h0 = g_gsum + g * 64;
    float h1[32];
    #pragma unroll 4
    for (int o = 0; o < 32; o++) {
        float acc = b1[o];
        #pragma unroll
        for (int k = 0; k < 64; k++) acc += h0[k] * w1[o * 64 + k];
        h1[o] = elu_(acc);
    }
    float h2[16];
    #pragma unroll
    for (int p = 0; p < 16; p++) {
        float acc = b2[p];
        #pragma unroll
        for (int o = 0; o < 32; o++) acc += h1[o] * w2[p * 32 + o];
        h2[p] = elu_(acc);
    }
    float acc = b3[0];
    #pragma unroll
    for (int q = 0; q < 16; q++) acc += h2[q] * w3[q];
    out[g] = acc;
}

// ---------------- launch ----------------------------------------------------------
extern "C" void kernel_launch(void* const* d_in, const int* in_sizes, int n_in,
                              void* d_out, int out_size) {
    const int*   z    = (const int*)d_in[0];
    const int*   ei   = (const int*)d_in[1];
    const int*   n2s  = (const int*)d_in[2];
    const int*   s2g  = (const int*)d_in[3];
    const float* ztab = (const float*)d_in[4];
    const float* tfW  = (const float*)d_in[5];
    const float* tfb  = (const float*)d_in[6];
    const float* ggcW = (const float*)d_in[7];
    const float* wih  = (const float*)d_in[8];
    const float* whh  = (const float*)d_in[9];
    const float* bih  = (const float*)d_in[10];
    const float* bhh  = (const float*)d_in[11];
    const float* w1   = (const float*)d_in[12];
    const float* b1   = (const float*)d_in[13];
    const float* w2   = (const float*)d_in[14];
    const float* b2   = (const float*)d_in[15];
    const float* w3   = (const float*)d_in[16];
    const float* b3   = (const float*)d_in[17];
    const int* src = ei;
    const int* dst = ei + N_EDGES;

    cudaFuncSetAttribute(k_gru_t, cudaFuncAttributeMaxDynamicSharedMemorySize, GRU_SMEM);
    cudaFuncSetAttribute(k_pre_t, cudaFuncAttributeMaxDynamicSharedMemorySize, PRE_SMEM);

    const int NBG = (N_NODES + GROWS - 1) / GROWS;  // 7813 gru tiles
    const int NBP = (N_NODES + PROWS - 1) / PROWS;  // 3907 pre tiles

    // order: profiler's fixed slot (4th launch) lands on k_gru_t
    k_pre1<<<206, 256>>>(ztab, tfW, tfb, ggcW);
    k_layer0<<<31250, 256>>>(z, ztab);
    k_scatter<<<78125, 256>>>(src, dst);
    k_gru_t<<<NBG, 256, GRU_SMEM>>>(wih, whh, bih, bhh, n2s, s2g, 0);   // <-- profiled
    k_pre2<<<100, 256>>>(ggcW);

    for (int l = 1; l < 5; l++) {
        k_pre_t<<<NBP, 256, PRE_SMEM>>>(z, tfW, l - 1);
        k_scatter<<<78125, 256>>>(src, dst);
        k_gru_t<<<NBG, 256, GRU_SMEM>>>(wih + l * 12288, whh + l * 12288,
                                        bih + l * 192, bhh + l * 192, n2s, s2g,
                                        (l == 4) ? 1 : 0);
    }

    k_head<<<1, 64>>>(w1, b1, w2, b2, w3, b3, (float*)d_out);
}

// round 10
// speedup vs baseline: 1.2847x; 1.2847x over previous
#include <cuda_runtime.h>
#include <cstdint>

#define N_NODES 500000
#define N_EDGES 1250000
#define N_GRAPH 64

typedef unsigned long long u64;
typedef unsigned int u32;

// ---------------- scratch (device globals; no allocation allowed) -----------
__device__ float g_x[N_NODES * 64];
__device__ float g_m[N_NODES * 64];
__device__ float g_agg[N_NODES * 64];
__device__ float g_u[4 * 100 * 64];
__device__ float g_Bm[4 * 64 * 64];
__device__ float g_v[4 * 100 * 64];
__device__ float g_t0m[100 * 64];
__device__ float g_gsum[64 * 64];

// ---------------- helpers ------------------------------------------------------
__device__ __forceinline__ float sigm(float x)  { return __fdividef(1.0f, 1.0f + __expf(-x)); }
__device__ __forceinline__ float tanh_(float x) { return __fdividef(2.0f, 1.0f + __expf(-2.0f * x)) - 1.0f; }
__device__ __forceinline__ float elu_(float x)  { return x > 0.0f ? x : (__expf(x) - 1.0f); }

__device__ __forceinline__ float tf32r(float x) {
    u32 r;
    asm("cvt.rna.tf32.f32 %0, %1;" : "=r"(r) : "f"(x));
    return __uint_as_float(r);
}
__device__ __forceinline__ u32 tf32u(float x) {
    u32 r;
    asm("cvt.rna.tf32.f32 %0, %1;" : "=r"(r) : "f"(x));
    return r;
}

#define F4F(v, e) ((e) == 0 ? (v).x : (e) == 1 ? (v).y : (e) == 2 ? (v).z : (v).w)
#define F4U(v, e) __float_as_uint(F4F(v, e))

// m16n8k8 tf32 mma
#define MMA4(c, a0, a1, a2, a3, b0, b1)                                          \
    asm volatile("mma.sync.aligned.m16n8k8.row.col.f32.tf32.tf32.f32 "           \
                 "{%0,%1,%2,%3}, {%4,%5,%6,%7}, {%8,%9}, {%0,%1,%2,%3};"          \
                 : "+f"((c)[0]), "+f"((c)[1]), "+f"((c)[2]), "+f"((c)[3])        \
                 : "r"(a0), "r"(a1), "r"(a2), "r"(a3), "r"(b0), "r"(b1))

// ---------------- precompute (also zeroes g_gsum) -------------------------------
__global__ void k_pre1(const float* __restrict__ ztab, const float* __restrict__ tfW,
                       const float* __restrict__ tfb, const float* __restrict__ ggcW) {
    int i = blockIdx.x * blockDim.x + threadIdx.x;
    if (i < 25600) {
        int j = i / 6400, r = (i % 6400) / 64, o = i % 64;
        const float* zt = ztab + (j + 1) * 6400 + r * 64;
        const float* w  = tfW + j * 8192 + o * 128 + 64;
        float acc = tfb[j * 64 + o];
        #pragma unroll
        for (int k = 0; k < 64; k++) acc += zt[k] * w[k];
        g_u[i] = acc;
    } else if (i < 41984) {
        int ii = i - 25600;
        int j = ii / 4096, o = (ii % 4096) / 64, k = ii % 64;
        const float* g = ggcW + (j + 1) * 4096 + o;
        const float* w = tfW + j * 8192 + k;
        float acc = 0.f;
        #pragma unroll
        for (int t = 0; t < 64; t++) acc += w[t * 128] * g[t * 64];
        g_Bm[ii] = acc;
    } else if (i < 48384) {
        int ii = i - 41984;
        int r = ii / 64, o = ii % 64;
        float acc = 0.f;
        #pragma unroll
        for (int k = 0; k < 64; k++) acc += ztab[r * 64 + k] * ggcW[k * 64 + o];
        g_t0m[ii] = acc;
    } else if (i < 52480) {
        g_gsum[i - 48384] = 0.f;
    }
}

__global__ void k_pre2(const float* __restrict__ ggcW) {
    int i = blockIdx.x * blockDim.x + threadIdx.x;
    if (i >= 25600) return;
    int j = i / 6400, r = (i % 6400) / 64, o = i % 64;
    const float* urow = g_u + j * 6400 + r * 64;
    const float* g = ggcW + (j + 1) * 4096 + o;
    float acc = 0.f;
    #pragma unroll
    for (int t = 0; t < 64; t++) acc += urow[t] * g[t * 64];
    g_v[i] = acc;
}

// ---------------- layer 0: lookups + zero agg -----------------------------------
__global__ void k_layer0(const int* __restrict__ z, const float* __restrict__ ztab) {
    int idx = blockIdx.x * 256 + threadIdx.x;  // N_NODES*16
    int n = idx >> 4, c = idx & 15;
    int r = __ldg(z + n);
    float4 a = ((const float4*)(ztab + r * 64))[c];
    ((float4*)(g_x + (size_t)n * 64))[c] = a;
    float4 b = ((const float4*)(g_t0m + r * 64))[c];
    ((float4*)(g_m + (size_t)n * 64))[c] = b;
    ((float4*)(g_agg + (size_t)n * 64))[c] = make_float4(0.f, 0.f, 0.f, 0.f);
}

// ---------------- edge scatter: agg[dst] += m[src] -------------------------------
__global__ void k_scatter(const int* __restrict__ src, const int* __restrict__ dst) {
    int idx = blockIdx.x * 256 + threadIdx.x;  // N_EDGES*16
    int e = idx >> 4, c = idx & 15;
    int s = __ldg(src + e), t = __ldg(dst + e);
    float4 v = ((const float4*)(g_m + (size_t)s * 64))[c];
    float* o = g_agg + (size_t)t * 64 + c * 4;
    atomicAdd(o + 0, v.x);
    atomicAdd(o + 1, v.y);
    atomicAdd(o + 2, v.z);
    atomicAdd(o + 3, v.w);
}

// ================= tensor (mma.sync tf32) layer kernels ==========================
// Fragment-major permuted layout: P[strip][half][lane][j], lane stride 20 floats
// (16B-aligned; conflict-free LDS.128). Persistent CTAs: weights staged ONCE,
// grid-strided tile loop stages only A tiles.

#define GROWS    64
#define GRU_CTAS 296
#define GB_BIAS 0                      // 384
#define GB_AAG  384                    // 4 strips * 2 * 32 * 20 = 5120
#define GB_AX   5504                   // 5120
#define GB_B    10624                  // 24 ntiles * 32 * 20 = 15360
#define GB_TOT  25984
#define GRU_SMEM (GB_TOT * 4)          // 103936 B -> 2 CTAs/SM

__global__ void __launch_bounds__(256, 2) k_gru_t(
        const float* __restrict__ wih, const float* __restrict__ whh,
        const float* __restrict__ bih, const float* __restrict__ bhh,
        const int* __restrict__ n2s, const int* __restrict__ s2g, int last) {
    extern __shared__ float sm[];
    float* sb = sm + GB_BIAS;
    int tid = threadIdx.x;

    // ---- one-time weight phase ----
    // stage wih permuted into GB_B
    for (int idx = tid; idx < 3072; idx += 256) {
        int row = idx >> 4, f4 = idx & 15;
        int nt = row >> 3, qr8 = row & 7;
        float4 v = ((const float4*)(wih + row * 64))[f4];
        float* p = sm + GB_B + (nt * 32 + qr8 * 4) * 20 + f4;
        p[0]  = tf32r(v.x);
        p[20] = tf32r(v.y);
        p[40] = tf32r(v.z);
        p[60] = tf32r(v.w);
    }
    __syncthreads();

    int w = tid >> 5, lane = tid & 31;
    int qr = lane >> 2, qc = lane & 3;

    // prefetch wih frags: warp w owns ntiles {w, w+8, w+16} -> d in [8w, 8w+8)
    float4 Bi4[3][4];
    #pragma unroll
    for (int g = 0; g < 3; g++) {
        const float4* pb = (const float4*)(sm + GB_B + ((w + 8 * g) * 32 + lane) * 20);
        #pragma unroll
        for (int j4 = 0; j4 < 4; j4++) Bi4[g][j4] = pb[j4];
    }
    __syncthreads();

    // overwrite GB_B with whh; load biases
    for (int i = tid; i < 384; i += 256) sb[i] = (i < 192) ? bih[i] : bhh[i - 192];
    for (int idx = tid; idx < 3072; idx += 256) {
        int row = idx >> 4, f4 = idx & 15;
        int nt = row >> 3, qr8 = row & 7;
        float4 v = ((const float4*)(whh + row * 64))[f4];
        float* p = sm + GB_B + (nt * 32 + qr8 * 4) * 20 + f4;
        p[0]  = tf32r(v.x);
        p[20] = tf32r(v.y);
        p[40] = tf32r(v.z);
        p[60] = tf32r(v.w);
    }

    int d0 = w * 8 + qc * 2;
    int jxo = 2 * w + (qc >> 1);
    int Lx0 = qr * 4 + ((2 * qc) & 3);
    int Lx1 = qr * 4 + ((2 * qc + 1) & 3);

    // ---- persistent tile loop ----
    #pragma unroll 1
    for (int tile = blockIdx.x; tile * GROWS < N_NODES; tile += GRU_CTAS) {
        int n0 = tile * GROWS;
        // stage A tiles (agg rounded, x raw); re-zero agg
        for (int idx = tid; idx < GROWS * 16; idx += 256) {
            int row = idx >> 4, f4 = idx & 15;
            int s = row >> 4, ih = (row >> 3) & 1, qr8 = row & 7;
            bool ok = (n0 + row) < N_NODES;
            size_t g = ok ? (size_t)(n0 + row) * 64 : 0;
            int ofs = ((s * 2 + ih) * 32 + qr8 * 4) * 20 + f4;
            float4 va = ((const float4*)(g_agg + g))[f4];
            float* pa = sm + GB_AAG + ofs;
            pa[0]  = tf32r(va.x);
            pa[20] = tf32r(va.y);
            pa[40] = tf32r(va.z);
            pa[60] = tf32r(va.w);
            float4 vx = ((const float4*)(g_x + g))[f4];
            float* px = sm + GB_AX + ofs;
            px[0]  = vx.x;
            px[20] = vx.y;
            px[40] = vx.z;
            px[60] = vx.w;
            if (ok && !last) ((float4*)(g_agg + g))[f4] = make_float4(0.f, 0.f, 0.f, 0.f);
        }
        __syncthreads();   // staging done (also covers whh staging on first iter)

        #pragma unroll 1
        for (int s = 0; s < GROWS / 16; s++) {
            float cgi[3][4] = {}, cgh[3][4] = {};
            // ---- GI = agg @ wih^T (Bi in regs) ----
            const float4* pa0 = (const float4*)(sm + GB_AAG + ((s * 2 + 0) * 32 + lane) * 20);
            const float4* pa1 = (const float4*)(sm + GB_AAG + ((s * 2 + 1) * 32 + lane) * 20);
            #pragma unroll
            for (int kh = 0; kh < 2; kh++) {
                float4 v00 = pa0[kh * 2], v01 = pa0[kh * 2 + 1];
                float4 v10 = pa1[kh * 2], v11 = pa1[kh * 2 + 1];
                u32 A0[8] = {F4U(v00,0), F4U(v00,1), F4U(v00,2), F4U(v00,3),
                             F4U(v01,0), F4U(v01,1), F4U(v01,2), F4U(v01,3)};
                u32 A1[8] = {F4U(v10,0), F4U(v10,1), F4U(v10,2), F4U(v10,3),
                             F4U(v11,0), F4U(v11,1), F4U(v11,2), F4U(v11,3)};
                #pragma unroll
                for (int k2 = 0; k2 < 4; k2++) {
                    #pragma unroll
                    for (int g = 0; g < 3; g++) {
                        MMA4(cgi[g], A0[2 * k2], A1[2 * k2], A0[2 * k2 + 1], A1[2 * k2 + 1],
                             F4U(Bi4[g][2 * kh + (k2 >> 1)], (2 * k2) & 3),
                             F4U(Bi4[g][2 * kh + (k2 >> 1)], (2 * k2 + 1) & 3));
                    }
                }
            }
            // ---- GH = x @ whh^T (Bh from smem) ----
            const float4* px0 = (const float4*)(sm + GB_AX + ((s * 2 + 0) * 32 + lane) * 20);
            const float4* px1 = (const float4*)(sm + GB_AX + ((s * 2 + 1) * 32 + lane) * 20);
            #pragma unroll
            for (int kh = 0; kh < 2; kh++) {
                float4 v00 = px0[kh * 2], v01 = px0[kh * 2 + 1];
                float4 v10 = px1[kh * 2], v11 = px1[kh * 2 + 1];
                u32 X0[8] = {tf32u(v00.x), tf32u(v00.y), tf32u(v00.z), tf32u(v00.w),
                             tf32u(v01.x), tf32u(v01.y), tf32u(v01.z), tf32u(v01.w)};
                u32 X1[8] = {tf32u(v10.x), tf32u(v10.y), tf32u(v10.z), tf32u(v10.w),
                             tf32u(v11.x), tf32u(v11.y), tf32u(v11.z), tf32u(v11.w)};
                #pragma unroll
                for (int g = 0; g < 3; g++) {
                    const float4* pb = (const float4*)(sm + GB_B + ((w + 8 * g) * 32 + lane) * 20)
                                       + kh * 2;
                    float4 b0v = pb[0], b1v = pb[1];
                    u32 BH[8] = {F4U(b0v,0), F4U(b0v,1), F4U(b0v,2), F4U(b0v,3),
                                 F4U(b1v,0), F4U(b1v,1), F4U(b1v,2), F4U(b1v,3)};
                    #pragma unroll
                    for (int k2 = 0; k2 < 4; k2++) {
                        MMA4(cgh[g], X0[2 * k2], X1[2 * k2], X0[2 * k2 + 1], X1[2 * k2 + 1],
                             BH[2 * k2], BH[2 * k2 + 1]);
                    }
                }
            }
            // ---- epilogue ----
            #pragma unroll
            for (int i = 0; i < 2; i++) {
                int r = s * 16 + qr + 8 * i;
                int n = n0 + r;
                int xb = GB_AX + (s * 2 + i) * 32 * 20;
                float xo0 = sm[xb + Lx0 * 20 + jxo];
                float xo1 = sm[xb + Lx1 * 20 + jxo];
                float out[2];
                #pragma unroll
                for (int j = 0; j < 2; j++) {
                    int d = d0 + j;
                    int ci = 2 * i + j;
                    float rr = sigm(cgi[0][ci] + sb[d] + cgh[0][ci] + sb[192 + d]);
                    float uu = sigm(cgi[1][ci] + sb[64 + d] + cgh[1][ci] + sb[256 + d]);
                    float nn = tanh_(cgi[2][ci] + sb[128 + d] + rr * (cgh[2][ci] + sb[320 + d]));
                    out[j] = (1.0f - uu) * nn + uu * (j ? xo1 : xo0);
                }
                if (n < N_NODES) {
                    if (!last) {
                        *(float2*)(g_x + (size_t)n * 64 + d0) = make_float2(out[0], out[1]);
                    } else {
                        int gofs = __ldg(s2g + __ldg(n2s + n)) * 64;
                        atomicAdd(g_gsum + gofs + d0, out[0]);
                        atomicAdd(g_gsum + gofs + d0 + 1, out[1]);
                    }
                }
            }
        }
        __syncthreads();   // protect A buffers before next tile's staging
    }
}

// ---------------- pre: persistent; B in regs once; buffer reused for A ----------
#define PROWS    128
#define PRE_CTAS 296
#define PRE_SMEM (10240 * 4)   // 8 strips * 2 * 32 * 20 == 16 ntiles * 32 * 20

__global__ void __launch_bounds__(256, 2) k_pre_t(
        const int* __restrict__ z, const float* __restrict__ tfW, int j) {
    extern __shared__ float sm[];
    int tid = threadIdx.x;

    // one-time: stage B = [W_left rows 0..63 | Bm rows 64..127] permuted
    const float* tw = tfW + j * 8192;
    const float* bm = g_Bm + j * 4096;
    for (int idx = tid; idx < 2048; idx += 256) {
        int row = idx >> 4, f4 = idx & 15;
        int nt = row >> 3, qr8 = row & 7;
        float4 v = (row < 64) ? ((const float4*)(tw + row * 128))[f4]
                              : ((const float4*)(bm + (row - 64) * 64))[f4];
        float* p = sm + (nt * 32 + qr8 * 4) * 20 + f4;
        p[0]  = tf32r(v.x);
        p[20] = tf32r(v.y);
        p[40] = tf32r(v.z);
        p[60] = tf32r(v.w);
    }
    __syncthreads();

    int w = tid >> 5, lane = tid & 31;
    int qr = lane >> 2, qc = lane & 3;

    float4 B4[2][4];   // warp w owns ntiles {w (xnew), w+8 (m)}
    #pragma unroll
    for (int g = 0; g < 2; g++) {
        const float4* pb = (const float4*)(sm + ((w + 8 * g) * 32 + lane) * 20);
        #pragma unroll
        for (int j4 = 0; j4 < 4; j4++) B4[g][j4] = pb[j4];
    }
    __syncthreads();   // buffer free for A staging

    int d0 = w * 8 + qc * 2;

    #pragma unroll 1
    for (int tile = blockIdx.x; tile * PROWS < N_NODES; tile += PRE_CTAS) {
        int n0 = tile * PROWS;
        // stage A (x raw) into the shared buffer
        for (int idx = tid; idx < PROWS * 16; idx += 256) {
            int row = idx >> 4, f4 = idx & 15;
            int s = row >> 4, ih = (row >> 3) & 1, qr8 = row & 7;
            bool ok = (n0 + row) < N_NODES;
            size_t g = ok ? (size_t)(n0 + row) * 64 : 0;
            float4 vx = ((const float4*)(g_x + g))[f4];
            float* px = sm + ((s * 2 + ih) * 32 + qr8 * 4) * 20 + f4;
            px[0]  = vx.x;
            px[20] = vx.y;
            px[40] = vx.z;
            px[60] = vx.w;
        }
        __syncthreads();

        #pragma unroll 1
        for (int s = 0; s < PROWS / 16; s++) {
            float cx[4] = {}, cm2[4] = {};
            const float4* px0 = (const float4*)(sm + ((s * 2 + 0) * 32 + lane) * 20);
            const float4* px1 = (const float4*)(sm + ((s * 2 + 1) * 32 + lane) * 20);
            #pragma unroll
            for (int kh = 0; kh < 2; kh++) {
                float4 v00 = px0[kh * 2], v01 = px0[kh * 2 + 1];
                float4 v10 = px1[kh * 2], v11 = px1[kh * 2 + 1];
                u32 X0[8] = {tf32u(v00.x), tf32u(v00.y), tf32u(v00.z), tf32u(v00.w),
                             tf32u(v01.x), tf32u(v01.y), tf32u(v01.z), tf32u(v01.w)};
                u32 X1[8] = {tf32u(v10.x), tf32u(v10.y), tf32u(v10.z), tf32u(v10.w),
                             tf32u(v11.x), tf32u(v11.y), tf32u(v11.z), tf32u(v11.w)};
                #pragma unroll
                for (int k2 = 0; k2 < 4; k2++) {
                    MMA4(cx, X0[2 * k2], X1[2 * k2], X0[2 * k2 + 1], X1[2 * k2 + 1],
                         F4U(B4[0][2 * kh + (k2 >> 1)], (2 * k2) & 3),
                         F4U(B4[0][2 * kh + (k2 >> 1)], (2 * k2 + 1) & 3));
                    MMA4(cm2, X0[2 * k2], X1[2 * k2], X0[2 * k2 + 1], X1[2 * k2 + 1],
                         F4U(B4[1][2 * kh + (k2 >> 1)], (2 * k2) & 3),
                         F4U(B4[1][2 * kh + (k2 >> 1)], (2 * k2 + 1) & 3));
                }
            }
            #pragma unroll
            for (int i = 0; i < 2; i++) {
                int r = s * 16 + qr + 8 * i;
                int n = n0 + r;
                if (n < N_NODES) {
                    int zr = __ldg(z + n);
                    const float* ur = g_u + j * 6400 + zr * 64;
                    const float* vr = g_v + j * 6400 + zr * 64;
                    float2 uu = __ldg((const float2*)(ur + d0));
                    float2 vv = __ldg((const float2*)(vr + d0));
                    *(float2*)(g_x + (size_t)n * 64 + d0) =
                        make_float2(cx[2 * i] + uu.x, cx[2 * i + 1] + uu.y);
                    *(float2*)(g_m + (size_t)n * 64 + d0) =
                        make_float2(cm2[2 * i] + vv.x, cm2[2 * i + 1] + vv.y);
                }
            }
        }
        __syncthreads();   // protect buffer before next tile's staging
    }
}

// ---------------- MLP head -------------------------------------------------------
__global__ void k_head(const float* __restrict__ w1, const float* __restrict__ b1,
                       const float* __restrict__ w2, const float* __restrict__ b2,
                       const float* __restrict__ w3, const float* __restrict__ b3,
                       float* __restrict__ out) {
    int g = threadIdx.x;
    if (g >= 64) return;
    const float* h0 = g_gsum + g * 64;
    float h1[32];
    #pragma unroll 4
    for (int o = 0; o < 32; o++) {
        float acc = b1[o];
        #pragma unroll
        for (int k = 0; k < 64; k++) acc += h0[k] * w1[o * 64 + k];
        h1[o] = elu_(acc);
    }
    float h2[16];
    #pragma unroll
    for (int p = 0; p < 16; p++) {
        float acc = b2[p];
        #pragma unroll
        for (int o = 0; o < 32; o++) acc += h1[o] * w2[p * 32 + o];
        h2[p] = elu_(acc);
    }
    float acc = b3[0];
    #pragma unroll
    for (int q = 0; q < 16; q++) acc += h2[q] * w3[q];
    out[g] = acc;
}

// ---------------- launch ----------------------------------------------------------
extern "C" void kernel_launch(void* const* d_in, const int* in_sizes, int n_in,
                              void* d_out, int out_size) {
    const int*   z    = (const int*)d_in[0];
    const int*   ei   = (const int*)d_in[1];
    const int*   n2s  = (const int*)d_in[2];
    const int*   s2g  = (const int*)d_in[3];
    const float* ztab = (const float*)d_in[4];
    const float* tfW  = (const float*)d_in[5];
    const float* tfb  = (const float*)d_in[6];
    const float* ggcW = (const float*)d_in[7];
    const float* wih  = (const float*)d_in[8];
    const float* whh  = (const float*)d_in[9];
    const float* bih  = (const float*)d_in[10];
    const float* bhh  = (const float*)d_in[11];
    const float* w1   = (const float*)d_in[12];
    const float* b1   = (const float*)d_in[13];
    const float* w2   = (const float*)d_in[14];
    const float* b2   = (const float*)d_in[15];
    const float* w3   = (const float*)d_in[16];
    const float* b3   = (const float*)d_in[17];
    const int* src = ei;
    const int* dst = ei + N_EDGES;

    cudaFuncSetAttribute(k_gru_t, cudaFuncAttributeMaxDynamicSharedMemorySize, GRU_SMEM);
    cudaFuncSetAttribute(k_pre_t, cudaFuncAttributeMaxDynamicSharedMemorySize, PRE_SMEM);

    // order: profiler's fixed slot (4th launch) lands on k_gru_t
    k_pre1<<<206, 256>>>(ztab, tfW, tfb, ggcW);
    k_layer0<<<31250, 256>>>(z, ztab);
    k_scatter<<<78125, 256>>>(src, dst);
    k_gru_t<<<GRU_CTAS, 256, GRU_SMEM>>>(wih, whh, bih, bhh, n2s, s2g, 0);  // <-- profiled
    k_pre2<<<100, 256>>>(ggcW);

    for (int l = 1; l < 5; l++) {
        k_pre_t<<<PRE_CTAS, 256, PRE_SMEM>>>(z, tfW, l - 1);
        k_scatter<<<78125, 256>>>(src, dst);
        k_gru_t<<<GRU_CTAS, 256, GRU_SMEM>>>(wih + l * 12288, whh + l * 12288,
                                             bih + l * 192, bhh + l * 192, n2s, s2g,
                                             (l == 4) ? 1 : 0);
    }

    k_head<<<1, 64>>>(w1, b1, w2, b2, w3, b3, (float*)d_out);
}

// round 11
// speedup vs baseline: 2.1108x; 1.6430x over previous
#include <cuda_runtime.h>
#include <cstdint>

#define N_NODES 500000
#define N_EDGES 1250000
#define N_GRAPH 64

typedef unsigned long long u64;
typedef unsigned int u32;

// ---------------- scratch (device globals; no allocation allowed) -----------
__device__ float g_x[N_NODES * 64];
__device__ float g_m[N_NODES * 64];
__device__ float g_agg[N_NODES * 64];
__device__ float g_u[4 * 100 * 64];
__device__ float g_Bm[4 * 64 * 64];
__device__ float g_v[4 * 100 * 64];
__device__ float g_t0m[100 * 64];
__device__ float g_gsum[64 * 64];

// ---------------- helpers ------------------------------------------------------
__device__ __forceinline__ float sigm(float x)  { return __fdividef(1.0f, 1.0f + __expf(-x)); }
__device__ __forceinline__ float tanh_(float x) { return __fdividef(2.0f, 1.0f + __expf(-2.0f * x)) - 1.0f; }
__device__ __forceinline__ float elu_(float x)  { return x > 0.0f ? x : (__expf(x) - 1.0f); }

__device__ __forceinline__ float tf32r(float x) {
    u32 r;
    asm("cvt.rna.tf32.f32 %0, %1;" : "=r"(r) : "f"(x));
    return __uint_as_float(r);
}
__device__ __forceinline__ u32 tf32u(float x) {
    u32 r;
    asm("cvt.rna.tf32.f32 %0, %1;" : "=r"(r) : "f"(x));
    return r;
}
__device__ __forceinline__ u32 smem_u32(const void* p) {
    u32 a;
    asm("{ .reg .u64 t; cvta.to.shared.u64 t, %1; cvt.u32.u64 %0, t; }" : "=r"(a) : "l"(p));
    return a;
}
__device__ __forceinline__ void cpa16(u32 saddr, const void* gaddr) {
    asm volatile("cp.async.cg.shared.global [%0], [%1], 16;" :: "r"(saddr), "l"(gaddr));
}
#define CP_COMMIT() asm volatile("cp.async.commit_group;" ::: "memory")
#define CP_WAIT1()  asm volatile("cp.async.wait_group 1;" ::: "memory")
#define CP_WAIT0()  asm volatile("cp.async.wait_group 0;" ::: "memory")

// m16n8k8 tf32 mma
#define MMA4(c, a0, a1, a2, a3, b0, b1)                                          \
    asm volatile("mma.sync.aligned.m16n8k8.row.col.f32.tf32.tf32.f32 "           \
                 "{%0,%1,%2,%3}, {%4,%5,%6,%7}, {%8,%9}, {%0,%1,%2,%3};"          \
                 : "+f"((c)[0]), "+f"((c)[1]), "+f"((c)[2]), "+f"((c)[3])        \
                 : "r"(a0), "r"(a1), "r"(a2), "r"(a3), "r"(b0), "r"(b1))

// ---------------- precompute (also zeroes g_gsum) -------------------------------
__global__ void k_pre1(const float* __restrict__ ztab, const float* __restrict__ tfW,
                       const float* __restrict__ tfb, const float* __restrict__ ggcW) {
    int i = blockIdx.x * blockDim.x + threadIdx.x;
    if (i < 25600) {
        int j = i / 6400, r = (i % 6400) / 64, o = i % 64;
        const float* zt = ztab + (j + 1) * 6400 + r * 64;
        const float* w  = tfW + j * 8192 + o * 128 + 64;
        float acc = tfb[j * 64 + o];
        #pragma unroll
        for (int k = 0; k < 64; k++) acc += zt[k] * w[k];
        g_u[i] = acc;
    } else if (i < 41984) {
        int ii = i - 25600;
        int j = ii / 4096, o = (ii % 4096) / 64, k = ii % 64;
        const float* g = ggcW + (j + 1) * 4096 + o;
        const float* w = tfW + j * 8192 + k;
        float acc = 0.f;
        #pragma unroll
        for (int t = 0; t < 64; t++) acc += w[t * 128] * g[t * 64];
        g_Bm[ii] = acc;
    } else if (i < 48384) {
        int ii = i - 41984;
        int r = ii / 64, o = ii % 64;
        float acc = 0.f;
        #pragma unroll
        for (int k = 0; k < 64; k++) acc += ztab[r * 64 + k] * ggcW[k * 64 + o];
        g_t0m[ii] = acc;
    } else if (i < 52480) {
        g_gsum[i - 48384] = 0.f;
    }
}

__global__ void k_pre2(const float* __restrict__ ggcW) {
    int i = blockIdx.x * blockDim.x + threadIdx.x;
    if (i >= 25600) return;
    int j = i / 6400, r = (i % 6400) / 64, o = i % 64;
    const float* urow = g_u + j * 6400 + r * 64;
    const float* g = ggcW + (j + 1) * 4096 + o;
    float acc = 0.f;
    #pragma unroll
    for (int t = 0; t < 64; t++) acc += urow[t] * g[t * 64];
    g_v[i] = acc;
}

// ---------------- layer 0: lookups + zero agg -----------------------------------
__global__ void k_layer0(const int* __restrict__ z, const float* __restrict__ ztab) {
    int idx = blockIdx.x * 256 + threadIdx.x;  // N_NODES*16
    int n = idx >> 4, c = idx & 15;
    int r = __ldg(z + n);
    float4 a = ((const float4*)(ztab + r * 64))[c];
    ((float4*)(g_x + (size_t)n * 64))[c] = a;
    float4 b = ((const float4*)(g_t0m + r * 64))[c];
    ((float4*)(g_m + (size_t)n * 64))[c] = b;
    ((float4*)(g_agg + (size_t)n * 64))[c] = make_float4(0.f, 0.f, 0.f, 0.f);
}

// ---------------- edge scatter: agg[dst] += m[src] -------------------------------
__global__ void k_scatter(const int* __restrict__ src, const int* __restrict__ dst) {
    int idx = blockIdx.x * 256 + threadIdx.x;  // N_EDGES*16
    int e = idx >> 4, c = idx & 15;
    int s = __ldg(src + e), t = __ldg(dst + e);
    float4 v = ((const float4*)(g_m + (size_t)s * 64))[c];
    float* o = g_agg + (size_t)t * 64 + c * 4;
    atomicAdd(o + 0, v.x);
    atomicAdd(o + 1, v.y);
    atomicAdd(o + 2, v.z);
    atomicAdd(o + 3, v.w);
}

// ================= tensor (mma.sync tf32) layer kernels ==========================
// Row-major stride-68 smem layout (272B rows: 16B-aligned, conflict-free scalar
// LDS). Persistent CTAs; cp.async double-buffered A staging; weights staged once.

#define GROWS    48
#define GRU_CTAS 296
#define GB_BIAS  0                     // 384 floats
#define GB_ABUF  384                   // 2 buffers x [agg 48*68 | x 48*68] = 2*6528
#define GB_B     13440                 // whh 192*68 = 13056
#define GB_TOT   26496
#define GRU_SMEM (GB_TOT * 4)          // 105984 B -> 2 CTAs/SM

__device__ __forceinline__ void gru_stage(u32 smb, int fbase, int n0, int tid) {
    #pragma unroll 1
    for (int idx = tid; idx < GROWS * 16; idx += 256) {
        int row = idx >> 4, f4 = idx & 15;
        int n = n0 + row;
        size_t g = (size_t)(n < N_NODES ? n : 0) * 64 + f4 * 4;
        u32 sa = smb + (u32)(fbase + row * 68 + f4 * 4) * 4;
        cpa16(sa, g_agg + g);
        cpa16(sa + 3264 * 4, g_x + g);
    }
}

__global__ void __launch_bounds__(256, 2) k_gru_t(
        const float* __restrict__ wih, const float* __restrict__ whh,
        const float* __restrict__ bih, const float* __restrict__ bhh,
        const int* __restrict__ n2s, const int* __restrict__ s2g, int last) {
    extern __shared__ float sm[];
    u32 smb = smem_u32(sm);
    float* sb = sm + GB_BIAS;
    int tid = threadIdx.x;
    int w = tid >> 5, lane = tid & 31, qr = lane >> 2, qc = lane & 3;

    // ---- one-time: stage wih (tf32-rounded) into GB_B ----
    for (int idx = tid; idx < 3072; idx += 256) {
        int row = idx >> 4, f4 = idx & 15;
        float4 v = ((const float4*)(wih + row * 64))[f4];
        float* p = sm + GB_B + row * 68 + f4 * 4;
        p[0] = tf32r(v.x); p[1] = tf32r(v.y); p[2] = tf32r(v.z); p[3] = tf32r(v.w);
    }
    __syncthreads();
    // prefetch wih frags: warp w owns n-tiles {w, w+8, w+16} -> d in [8w, 8w+8)
    u32 Bi[3][8][2];
    #pragma unroll
    for (int g = 0; g < 3; g++) {
        const float* pb = sm + GB_B + ((w + 8 * g) * 8 + qr) * 68 + qc;
        #pragma unroll
        for (int kt = 0; kt < 8; kt++) {
            Bi[g][kt][0] = __float_as_uint(pb[kt * 8]);
            Bi[g][kt][1] = __float_as_uint(pb[kt * 8 + 4]);
        }
    }
    __syncthreads();
    // overwrite GB_B with whh (rounded); biases
    for (int i = tid; i < 384; i += 256) sb[i] = (i < 192) ? bih[i] : bhh[i - 192];
    for (int idx = tid; idx < 3072; idx += 256) {
        int row = idx >> 4, f4 = idx & 15;
        float4 v = ((const float4*)(whh + row * 64))[f4];
        float* p = sm + GB_B + row * 68 + f4 * 4;
        p[0] = tf32r(v.x); p[1] = tf32r(v.y); p[2] = tf32r(v.z); p[3] = tf32r(v.w);
    }

    int d0 = w * 8 + qc * 2;
    int p = 0;
    int tile = blockIdx.x;
    gru_stage(smb, GB_ABUF, tile * GROWS, tid);   // prologue prefetch
    CP_COMMIT();

    #pragma unroll 1
    for (; tile * GROWS < N_NODES; tile += GRU_CTAS) {
        int n0 = tile * GROWS;
        int ntile = tile + GRU_CTAS;
        bool hn = ntile * GROWS < N_NODES;
        if (hn) {
            gru_stage(smb, GB_ABUF + (p ^ 1) * 6528, ntile * GROWS, tid);
            CP_COMMIT();
            CP_WAIT1();
        } else {
            CP_WAIT0();
        }
        __syncthreads();   // buf[p] ready (also orders whh/bias staging on iter 0)

        int ab = GB_ABUF + p * 6528;
        int xb = ab + 3264;

        // re-zero this tile's agg rows in global (next layer's scatter target)
        if (!last) {
            #pragma unroll 1
            for (int idx = tid; idx < GROWS * 16; idx += 256) {
                int row = idx >> 4, f4 = idx & 15;
                int n = n0 + row;
                if (n < N_NODES)
                    ((float4*)(g_agg + (size_t)n * 64))[f4] = make_float4(0.f, 0.f, 0.f, 0.f);
            }
        }

        #pragma unroll 1
        for (int s = 0; s < GROWS / 16; s++) {
            float cgi[3][4] = {}, cgh[3][4] = {};
            // ---- GI = agg @ wih^T (Bi in regs; agg raw -> cvt at load) ----
            const float* pa = sm + ab + (s * 16 + qr) * 68 + qc;
            #pragma unroll
            for (int kt = 0; kt < 8; kt++) {
                u32 a0 = tf32u(pa[kt * 8]);
                u32 a1 = tf32u(pa[kt * 8 + 8 * 68]);
                u32 a2 = tf32u(pa[kt * 8 + 4]);
                u32 a3 = tf32u(pa[kt * 8 + 8 * 68 + 4]);
                MMA4(cgi[0], a0, a1, a2, a3, Bi[0][kt][0], Bi[0][kt][1]);
                MMA4(cgi[1], a0, a1, a2, a3, Bi[1][kt][0], Bi[1][kt][1]);
                MMA4(cgi[2], a0, a1, a2, a3, Bi[2][kt][0], Bi[2][kt][1]);
            }
            // ---- GH = x @ whh^T (whh pre-rounded in smem; x raw -> cvt) ----
            const float* px = sm + xb + (s * 16 + qr) * 68 + qc;
            const float* pb0 = sm + GB_B + (w * 8 + qr) * 68 + qc;
            const float* pb1 = pb0 + 64 * 68;
            const float* pb2 = pb0 + 128 * 68;
            #pragma unroll
            for (int kt = 0; kt < 8; kt++) {
                u32 x0 = tf32u(px[kt * 8]);
                u32 x1 = tf32u(px[kt * 8 + 8 * 68]);
                u32 x2 = tf32u(px[kt * 8 + 4]);
                u32 x3 = tf32u(px[kt * 8 + 8 * 68 + 4]);
                MMA4(cgh[0], x0, x1, x2, x3,
                     __float_as_uint(pb0[kt * 8]), __float_as_uint(pb0[kt * 8 + 4]));
                MMA4(cgh[1], x0, x1, x2, x3,
                     __float_as_uint(pb1[kt * 8]), __float_as_uint(pb1[kt * 8 + 4]));
                MMA4(cgh[2], x0, x1, x2, x3,
                     __float_as_uint(pb2[kt * 8]), __float_as_uint(pb2[kt * 8 + 4]));
            }
            // ---- epilogue ----
            #pragma unroll
            for (int i = 0; i < 2; i++) {
                int r = s * 16 + qr + 8 * i;
                int n = n0 + r;
                float2 xo = *(const float2*)(sm + xb + r * 68 + d0);
                float out[2];
                #pragma unroll
                for (int j = 0; j < 2; j++) {
                    int d = d0 + j;
                    int ci = 2 * i + j;
                    float rr = sigm(cgi[0][ci] + sb[d] + cgh[0][ci] + sb[192 + d]);
                    float uu = sigm(cgi[1][ci] + sb[64 + d] + cgh[1][ci] + sb[256 + d]);
                    float nn = tanh_(cgi[2][ci] + sb[128 + d] + rr * (cgh[2][ci] + sb[320 + d]));
                    out[j] = (1.0f - uu) * nn + uu * (j ? xo.y : xo.x);
                }
                if (n < N_NODES) {
                    if (!last) {
                        *(float2*)(g_x + (size_t)n * 64 + d0) = make_float2(out[0], out[1]);
                    } else {
                        int gofs = __ldg(s2g + __ldg(n2s + n)) * 64;
                        atomicAdd(g_gsum + gofs + d0, out[0]);
                        atomicAdd(g_gsum + gofs + d0 + 1, out[1]);
                    }
                }
            }
        }
        __syncthreads();   // everyone done with buf[p] before restaging it
        p ^= 1;
    }
}

// ---------------- pre: persistent, cp.async double-buffered --------------------
#define PROWS    64
#define PRE_CTAS 296
#define PRE_SMEM (8704 * 4)   // 2 buffers x 64*68 floats (B staged through them once)

__device__ __forceinline__ void pre_stage(u32 smb, int fbase, int n0, int tid) {
    #pragma unroll 1
    for (int idx = tid; idx < PROWS * 16; idx += 256) {
        int row = idx >> 4, f4 = idx & 15;
        int n = n0 + row;
        size_t g = (size_t)(n < N_NODES ? n : 0) * 64 + f4 * 4;
        cpa16(smb + (u32)(fbase + row * 68 + f4 * 4) * 4, g_x + g);
    }
}

__global__ void __launch_bounds__(256, 2) k_pre_t(
        const int* __restrict__ z, const float* __restrict__ tfW, int j) {
    extern __shared__ float sm[];
    u32 smb = smem_u32(sm);
    int tid = threadIdx.x;
    int w = tid >> 5, lane = tid & 31, qr = lane >> 2, qc = lane & 3;

    // one-time: stage B = [W_left 0..63 | Bm 64..127] across both buffers
    const float* tw = tfW + j * 8192;
    const float* bm = g_Bm + j * 4096;
    for (int idx = tid; idx < 2048; idx += 256) {
        int row = idx >> 4, f4 = idx & 15;
        float4 v = (row < 64) ? ((const float4*)(tw + row * 128))[f4]
                              : ((const float4*)(bm + (row - 64) * 64))[f4];
        float* p = sm + row * 68 + f4 * 4;
        p[0] = tf32r(v.x); p[1] = tf32r(v.y); p[2] = tf32r(v.z); p[3] = tf32r(v.w);
    }
    __syncthreads();
    u32 B4[2][8][2];   // warp w owns ntiles {w (xnew), w+8 (m)}
    #pragma unroll
    for (int g = 0; g < 2; g++) {
        const float* pb = sm + ((w + 8 * g) * 8 + qr) * 68 + qc;
        #pragma unroll
        for (int kt = 0; kt < 8; kt++) {
            B4[g][kt][0] = __float_as_uint(pb[kt * 8]);
            B4[g][kt][1] = __float_as_uint(pb[kt * 8 + 4]);
        }
    }
    __syncthreads();

    int d0 = w * 8 + qc * 2;
    int p = 0;
    int tile = blockIdx.x;
    pre_stage(smb, 0, tile * PROWS, tid);
    CP_COMMIT();

    #pragma unroll 1
    for (; tile * PROWS < N_NODES; tile += PRE_CTAS) {
        int n0 = tile * PROWS;
        int ntile = tile + PRE_CTAS;
        bool hn = ntile * PROWS < N_NODES;
        if (hn) {
            pre_stage(smb, (p ^ 1) * 4352, ntile * PROWS, tid);
            CP_COMMIT();
            CP_WAIT1();
        } else {
            CP_WAIT0();
        }
        __syncthreads();

        int xbase = p * 4352;
        #pragma unroll 1
        for (int s = 0; s < PROWS / 16; s++) {
            float cx[4] = {}, cm2[4] = {};
            const float* px = sm + xbase + (s * 16 + qr) * 68 + qc;
            #pragma unroll
            for (int kt = 0; kt < 8; kt++) {
                u32 x0 = tf32u(px[kt * 8]);
                u32 x1 = tf32u(px[kt * 8 + 8 * 68]);
                u32 x2 = tf32u(px[kt * 8 + 4]);
                u32 x3 = tf32u(px[kt * 8 + 8 * 68 + 4]);
                MMA4(cx, x0, x1, x2, x3, B4[0][kt][0], B4[0][kt][1]);
                MMA4(cm2, x0, x1, x2, x3, B4[1][kt][0], B4[1][kt][1]);
            }
            #pragma unroll
            for (int i = 0; i < 2; i++) {
                int r = s * 16 + qr + 8 * i;
                int n = n0 + r;
                if (n < N_NODES) {
                    int zr = __ldg(z + n);
                    const float* ur = g_u + j * 6400 + zr * 64;
                    const float* vr = g_v + j * 6400 + zr * 64;
                    float2 uu = __ldg((const float2*)(ur + d0));
                    float2 vv = __ldg((const float2*)(vr + d0));
                    *(float2*)(g_x + (size_t)n * 64 + d0) =
                        make_float2(cx[2 * i] + uu.x, cx[2 * i + 1] + uu.y);
                    *(float2*)(g_m + (size_t)n * 64 + d0) =
                        make_float2(cm2[2 * i] + vv.x, cm2[2 * i + 1] + vv.y);
                }
            }
        }
        __syncthreads();
        p ^= 1;
    }
}

// ---------------- MLP head -------------------------------------------------------
__global__ void k_head(const float* __restrict__ w1, const float* __restrict__ b1,
                       const float* __restrict__ w2, const float* __restrict__ b2,
                       const float* __restrict__ w3, const float* __restrict__ b3,
                       float* __restrict__ out) {
    int g = threadIdx.x;
    if (g >= 64) return;
    const float* h0 = g_gsum + g * 64;
    float h1[32];
    #pragma unroll 4
    for (int o = 0; o < 32; o++) {
        float acc = b1[o];
        #pragma unroll
        for (int k = 0; k < 64; k++) acc += h0[k] * w1[o * 64 + k];
        h1[o] = elu_(acc);
    }
    float h2[16];
    #pragma unroll
    for (int p = 0; p < 16; p++) {
        float acc = b2[p];
        #pragma unroll
        for (int o = 0; o < 32; o++) acc += h1[o] * w2[p * 32 + o];
        h2[p] = elu_(acc);
    }
    float acc = b3[0];
    #pragma unroll
    for (int q = 0; q < 16; q++) acc += h2[q] * w3[q];
    out[g] = acc;
}

// ---------------- launch ----------------------------------------------------------
extern "C" void kernel_launch(void* const* d_in, const int* in_sizes, int n_in,
                              void* d_out, int out_size) {
    const int*   z    = (const int*)d_in[0];
    const int*   ei   = (const int*)d_in[1];
    const int*   n2s  = (const int*)d_in[2];
    const int*   s2g  = (const int*)d_in[3];
    const float* ztab = (const float*)d_in[4];
    const float* tfW  = (const float*)d_in[5];
    const float* tfb  = (const float*)d_in[6];
    const float* ggcW = (const float*)d_in[7];
    const float* wih  = (const float*)d_in[8];
    const float* whh  = (const float*)d_in[9];
    const float* bih  = (const float*)d_in[10];
    const float* bhh  = (const float*)d_in[11];
    const float* w1   = (const float*)d_in[12];
    const float* b1   = (const float*)d_in[13];
    const float* w2   = (const float*)d_in[14];
    const float* b2   = (const float*)d_in[15];
    const float* w3   = (const float*)d_in[16];
    const float* b3   = (const float*)d_in[17];
    const int* src = ei;
    const int* dst = ei + N_EDGES;

    cudaFuncSetAttribute(k_gru_t, cudaFuncAttributeMaxDynamicSharedMemorySize, GRU_SMEM);
    cudaFuncSetAttribute(k_pre_t, cudaFuncAttributeMaxDynamicSharedMemorySize, PRE_SMEM);

    // order: profiler's fixed slot (4th launch) lands on k_gru_t
    k_pre1<<<206, 256>>>(ztab, tfW, tfb, ggcW);
    k_layer0<<<31250, 256>>>(z, ztab);
    k_scatter<<<78125, 256>>>(src, dst);
    k_gru_t<<<GRU_CTAS, 256, GRU_SMEM>>>(wih, whh, bih, bhh, n2s, s2g, 0);  // <-- profiled
    k_pre2<<<100, 256>>>(ggcW);

    for (int l = 1; l < 5; l++) {
        k_pre_t<<<PRE_CTAS, 256, PRE_SMEM>>>(z, tfW, l - 1);
        k_scatter<<<78125, 256>>>(src, dst);
        k_gru_t<<<GRU_CTAS, 256, GRU_SMEM>>>(wih + l * 12288, whh + l * 12288,
                                             bih + l * 192, bhh + l * 192, n2s, s2g,
                                             (l == 4) ? 1 : 0);
    }

    k_head<<<1, 64>>>(w1, b1, w2, b2, w3, b3, (float*)d_out);
}